// round 4
// baseline (speedup 1.0000x reference)
#include <cuda_runtime.h>

typedef unsigned long long u64;
#define DEV __device__ __forceinline__

DEV u64 pk2(float v) {
    u64 r; asm("mov.b64 %0, {%1, %1};" : "=l"(r) : "f"(v)); return r;
}
DEV void fma2(u64& d, u64 a, u64 b) {
    asm("fma.rn.f32x2 %0, %1, %2, %0;" : "+l"(d) : "l"(a), "l"(b));
}
DEV void upk2(u64 v, float& lo, float& hi) {
    asm("mov.b64 {%0, %1}, %2;" : "=f"(lo), "=f"(hi) : "l"(v));
}

constexpr int BATCH = 16384;
constexpr int F1    = 512;
constexpr int HID   = 256;
constexpr int NOUT  = 128;
constexpr int BT    = 4;      // batch elements per CTA
constexpr int MT    = 48;     // rows per CTA
constexpr int KB    = 16;     // k-slice
constexpr int THREADS = 256;
constexpr int ASTR  = 52;     // transposed activation plane stride (48 rows + pad)

constexpr int HT_ELEMS = HID * ASTR;       // 13312 (k-major activations, in-place mix)
constexpr int WS_ELEMS = 2 * KB * HID;     // 8192  (weight double buffer)
constexpr int XT_ELEMS = 2 * KB * ASTR;    // 1664  (layer-1 x slices, transposed, dbl buf)
constexpr int A_ELEMS  = 144;
constexpr int SMEM_BYTES = (HT_ELEMS + WS_ELEMS + XT_ELEMS + A_ELEMS + 16) * 4;  // ~93KB

// Fixed ECG graph neighbor lists (incl. self), 42 nonzeros of the 12x12 A_norm.
__device__ constexpr int NBR_OFF[13] = {0,5,11,16,20,23,26,28,31,34,37,40,42};
__device__ constexpr int NBR[42] = {
    0,1,2,3,4,
    0,1,2,3,4,5,
    0,1,2,3,5,
    0,1,2,3,
    0,1,4,
    1,2,5,
    6,7,
    6,7,8,
    7,8,9,
    8,9,10,
    9,10,11,
    10,11
};

// In-place A-mix on transposed buffer HT[col][12b..12b+11]; optional fused epilogue.
template<int NCOL, bool RELU, bool FINAL>
DEV void mix_phase(float* HT, const float* Am, const float* __restrict__ bias,
                   float* __restrict__ out, long long obase, int tid)
{
    constexpr int NT = NCOL * BT / THREADS;   // tasks per thread
    #pragma unroll
    for (int s = 0; s < NT; s++) {
        int t   = tid + s * THREADS;
        int b   = t & (BT - 1);
        int col = t >> 2;
        float* hp = HT + col * ASTR + b * 12;
        float4 h0 = *(const float4*)(hp);
        float4 h1 = *(const float4*)(hp + 4);
        float4 h2 = *(const float4*)(hp + 8);
        float h[12] = {h0.x,h0.y,h0.z,h0.w, h1.x,h1.y,h1.z,h1.w, h2.x,h2.y,h2.z,h2.w};
        float bv = __ldg(bias + col);
        float y[12];
        #pragma unroll
        for (int l = 0; l < 12; l++) {
            float acc = 0.f;
            #pragma unroll
            for (int q = NBR_OFF[l]; q < NBR_OFF[l + 1]; q++) {
                int m = NBR[q];
                acc += Am[l * 12 + m] * h[m];
            }
            y[l] = acc + bv;
            if (RELU) y[l] = fmaxf(y[l], 0.f);
        }
        __syncthreads();   // all reads of P complete before overwrite
        if (!FINAL) {
            *(float4*)(hp)     = make_float4(y[0], y[1], y[2],  y[3]);
            *(float4*)(hp + 4) = make_float4(y[4], y[5], y[6],  y[7]);
            *(float4*)(hp + 8) = make_float4(y[8], y[9], y[10], y[11]);
        } else {
            float sum = 0.f, mx = -3.402823466e38f;
            #pragma unroll
            for (int l = 0; l < 12; l++) { sum += y[l]; mx = fmaxf(mx, y[l]); }
            float* op = out + (obase + b) * (2 * NOUT);
            op[col]        = sum * (1.0f / 12.0f);
            op[NOUT + col] = mx;
        }
    }
}

__global__ void __launch_bounds__(THREADS, 2)
ecg_fused(const float* __restrict__ x,
          const float* __restrict__ W1, const float* __restrict__ b1,
          const float* __restrict__ W2, const float* __restrict__ b2,
          const float* __restrict__ W3, const float* __restrict__ b3,
          float* __restrict__ out)
{
    extern __shared__ float sm[];
    float* HT  = sm;                  // [HID][ASTR] transposed activations
    float* Wsb = sm + HT_ELEMS;       // weight slices, double buffered
    float* XT  = Wsb + WS_ELEMS;      // layer-1 x slices, transposed, double buffered
    float* Am  = XT + XT_ELEMS;       // 12x12 normalized adjacency

    const int tid  = threadIdx.x;
    const int lane = tid & 31;
    const int w    = tid >> 5;        // 0..7
    const int tx   = lane & 3;        // 4 col sub-groups in warp
    const int tyl  = lane >> 2;       // 8 row threads in warp
    const int rg   = w & 1;           // row group (0..1)
    const int cg   = w >> 1;          // col group (0..3)
    const int r0   = rg * 24 + tyl * 3;           // 3 rows
    const int c0   = cg * 64 + tx * 16;           // 16 cols (N=256 layers)
    const int c0_3 = cg * 32 + tx * 8;            // 8 cols  (N=128 layer)
    const long long rowbase = (long long)blockIdx.x * MT;
    const long long obase   = (long long)blockIdx.x * BT;

    // Build A_norm once per CTA: adj + 2*I (buffer eye + PyG self-loop), sym-normalized.
    if (tid == 0) {
        float a[12][12];
        for (int i = 0; i < 12; i++)
            for (int j = 0; j < 12; j++) a[i][j] = (i == j) ? 2.0f : 0.0f;
        const int ei[15] = {0,0,1,0,1,2,0,1,1,2,6,7,8,9,10};
        const int ej[15] = {1,2,2,3,3,3,4,4,5,5,7,8,9,10,11};
        for (int e = 0; e < 15; e++) { a[ei[e]][ej[e]] = 1.0f; a[ej[e]][ei[e]] = 1.0f; }
        float dinv[12];
        for (int i = 0; i < 12; i++) {
            float s = 0.f;
            for (int j = 0; j < 12; j++) s += a[i][j];
            dinv[i] = 1.0f / sqrtf(s);
        }
        for (int i = 0; i < 12; i++)
            for (int j = 0; j < 12; j++)
                Am[i * 12 + j] = dinv[i] * a[i][j] * dinv[j];
    }

    // staging assignments
    const int wk  = tid >> 4;            // 0..15 k within weight slice
    const int wn  = (tid & 15) << 4;     // 0..240 (16 floats per thread, N=256)
    const int wn3 = (tid & 15) << 3;     // 0..120 (8 floats per thread, N=128)
    const int xr  = tid >> 2;            // 0..63, active <48
    const int xc  = (tid & 3) << 2;      // 0,4,8,12
    const bool xact = tid < (MT * 4);    // 192 threads

    // ================= Layer 1: P = X(48x512) @ W1(512x256) =================
    u64 acc[3][8];
    #pragma unroll
    for (int i = 0; i < 3; i++)
        #pragma unroll
        for (int j = 0; j < 8; j++) acc[i][j] = 0ull;

    {
        #pragma unroll
        for (int v = 0; v < 4; v++) {
            float4 wv = *(const float4*)(W1 + (size_t)wk * HID + wn + v * 4);
            *(float4*)(Wsb + wk * HID + wn + v * 4) = wv;
        }
        if (xact) {
            float4 xv = *(const float4*)(x + (rowbase + xr) * F1 + xc);
            XT[(xc + 0) * ASTR + xr] = xv.x;
            XT[(xc + 1) * ASTR + xr] = xv.y;
            XT[(xc + 2) * ASTR + xr] = xv.z;
            XT[(xc + 3) * ASTR + xr] = xv.w;
        }
    }
    __syncthreads();

    for (int kb = 0; kb < F1; kb += KB) {
        const int cur = (kb / KB) & 1;
        const int nxt = cur ^ 1;
        float4 nw[4], nx;
        const bool more = (kb + KB) < F1;
        if (more) {
            #pragma unroll
            for (int v = 0; v < 4; v++)
                nw[v] = *(const float4*)(W1 + (size_t)(kb + KB + wk) * HID + wn + v * 4);
            if (xact) nx = *(const float4*)(x + (rowbase + xr) * F1 + kb + KB + xc);
        }
        const float* Wc = Wsb + cur * KB * HID;
        const float* Ac = XT + cur * KB * ASTR;
        #pragma unroll
        for (int k = 0; k < KB; k++) {
            u64 a0 = pk2(Ac[k * ASTR + r0 + 0]);
            u64 a1 = pk2(Ac[k * ASTR + r0 + 1]);
            u64 a2 = pk2(Ac[k * ASTR + r0 + 2]);
            #pragma unroll
            for (int j = 0; j < 4; j++) {
                ulonglong2 wv = *(const ulonglong2*)(Wc + k * HID + c0 + (j << 2));
                fma2(acc[0][2*j],   a0, wv.x); fma2(acc[0][2*j+1], a0, wv.y);
                fma2(acc[1][2*j],   a1, wv.x); fma2(acc[1][2*j+1], a1, wv.y);
                fma2(acc[2][2*j],   a2, wv.x); fma2(acc[2][2*j+1], a2, wv.y);
            }
        }
        if (more) {
            #pragma unroll
            for (int v = 0; v < 4; v++)
                *(float4*)(Wsb + nxt * KB * HID + wk * HID + wn + v * 4) = nw[v];
            if (xact) {
                float* xd = XT + nxt * KB * ASTR;
                xd[(xc + 0) * ASTR + xr] = nx.x;
                xd[(xc + 1) * ASTR + xr] = nx.y;
                xd[(xc + 2) * ASTR + xr] = nx.z;
                xd[(xc + 3) * ASTR + xr] = nx.w;
            }
        }
        __syncthreads();
    }

    // P1 -> HT (transposed). acc[i][jj] = cols c0 + 4*(jj>>1) + 2*(jj&1) + {0,1}
    #pragma unroll
    for (int i = 0; i < 3; i++)
        #pragma unroll
        for (int jj = 0; jj < 8; jj++) {
            int col = c0 + ((jj >> 1) << 2) + ((jj & 1) << 1);
            float lo, hi; upk2(acc[i][jj], lo, hi);
            HT[col * ASTR + r0 + i]       = lo;
            HT[(col + 1) * ASTR + r0 + i] = hi;
        }
    __syncthreads();
    mix_phase<HID, true, false>(HT, Am, b1, out, obase, tid);
    __syncthreads();

    // ================= Layer 2: P = H1(48x256) @ W2(256x256) =================
    #pragma unroll
    for (int i = 0; i < 3; i++)
        #pragma unroll
        for (int j = 0; j < 8; j++) acc[i][j] = 0ull;

    {
        #pragma unroll
        for (int v = 0; v < 4; v++) {
            float4 wv = *(const float4*)(W2 + (size_t)wk * HID + wn + v * 4);
            *(float4*)(Wsb + wk * HID + wn + v * 4) = wv;
        }
    }
    __syncthreads();

    for (int kb = 0; kb < HID; kb += KB) {
        const int cur = (kb / KB) & 1;
        const int nxt = cur ^ 1;
        float4 nw[4];
        const bool more = (kb + KB) < HID;
        if (more) {
            #pragma unroll
            for (int v = 0; v < 4; v++)
                nw[v] = *(const float4*)(W2 + (size_t)(kb + KB + wk) * HID + wn + v * 4);
        }
        const float* Wc = Wsb + cur * KB * HID;
        const float* Ac = HT + kb * ASTR;
        #pragma unroll
        for (int k = 0; k < KB; k++) {
            u64 a0 = pk2(Ac[k * ASTR + r0 + 0]);
            u64 a1 = pk2(Ac[k * ASTR + r0 + 1]);
            u64 a2 = pk2(Ac[k * ASTR + r0 + 2]);
            #pragma unroll
            for (int j = 0; j < 4; j++) {
                ulonglong2 wv = *(const ulonglong2*)(Wc + k * HID + c0 + (j << 2));
                fma2(acc[0][2*j],   a0, wv.x); fma2(acc[0][2*j+1], a0, wv.y);
                fma2(acc[1][2*j],   a1, wv.x); fma2(acc[1][2*j+1], a1, wv.y);
                fma2(acc[2][2*j],   a2, wv.x); fma2(acc[2][2*j+1], a2, wv.y);
            }
        }
        if (more) {
            #pragma unroll
            for (int v = 0; v < 4; v++)
                *(float4*)(Wsb + nxt * KB * HID + wk * HID + wn + v * 4) = nw[v];
        }
        __syncthreads();
    }

    #pragma unroll
    for (int i = 0; i < 3; i++)
        #pragma unroll
        for (int jj = 0; jj < 8; jj++) {
            int col = c0 + ((jj >> 1) << 2) + ((jj & 1) << 1);
            float lo, hi; upk2(acc[i][jj], lo, hi);
            HT[col * ASTR + r0 + i]       = lo;
            HT[(col + 1) * ASTR + r0 + i] = hi;
        }
    __syncthreads();
    mix_phase<HID, true, false>(HT, Am, b2, out, obase, tid);
    __syncthreads();

    // ================= Layer 3: P = H2(48x256) @ W3(256x128) =================
    u64 acc3[3][4];
    #pragma unroll
    for (int i = 0; i < 3; i++)
        #pragma unroll
        for (int j = 0; j < 4; j++) acc3[i][j] = 0ull;

    {
        #pragma unroll
        for (int v = 0; v < 2; v++) {
            float4 wv = *(const float4*)(W3 + (size_t)wk * NOUT + wn3 + v * 4);
            *(float4*)(Wsb + wk * NOUT + wn3 + v * 4) = wv;
        }
    }
    __syncthreads();

    for (int kb = 0; kb < HID; kb += KB) {
        const int cur = (kb / KB) & 1;
        const int nxt = cur ^ 1;
        float4 nw[2];
        const bool more = (kb + KB) < HID;
        if (more) {
            #pragma unroll
            for (int v = 0; v < 2; v++)
                nw[v] = *(const float4*)(W3 + (size_t)(kb + KB + wk) * NOUT + wn3 + v * 4);
        }
        const float* Wc = Wsb + cur * KB * NOUT;
        const float* Ac = HT + kb * ASTR;
        #pragma unroll
        for (int k = 0; k < KB; k++) {
            u64 a0 = pk2(Ac[k * ASTR + r0 + 0]);
            u64 a1 = pk2(Ac[k * ASTR + r0 + 1]);
            u64 a2 = pk2(Ac[k * ASTR + r0 + 2]);
            #pragma unroll
            for (int j = 0; j < 2; j++) {
                ulonglong2 wv = *(const ulonglong2*)(Wc + k * NOUT + c0_3 + (j << 2));
                fma2(acc3[0][2*j],   a0, wv.x); fma2(acc3[0][2*j+1], a0, wv.y);
                fma2(acc3[1][2*j],   a1, wv.x); fma2(acc3[1][2*j+1], a1, wv.y);
                fma2(acc3[2][2*j],   a2, wv.x); fma2(acc3[2][2*j+1], a2, wv.y);
            }
        }
        if (more) {
            #pragma unroll
            for (int v = 0; v < 2; v++)
                *(float4*)(Wsb + nxt * KB * NOUT + wk * NOUT + wn3 + v * 4) = nw[v];
        }
        __syncthreads();
    }

    #pragma unroll
    for (int i = 0; i < 3; i++)
        #pragma unroll
        for (int jj = 0; jj < 4; jj++) {
            int col = c0_3 + ((jj >> 1) << 2) + ((jj & 1) << 1);
            float lo, hi; upk2(acc3[i][jj], lo, hi);
            HT[col * ASTR + r0 + i]       = lo;
            HT[(col + 1) * ASTR + r0 + i] = hi;
        }
    __syncthreads();
    // final mix fused with mean/max epilogue, writes global out
    mix_phase<NOUT, false, true>(HT, Am, b3, out, obase, tid);
}

extern "C" void kernel_launch(void* const* d_in, const int* in_sizes, int n_in,
                              void* d_out, int out_size)
{
    const float* x  = (const float*)d_in[0];
    const float* W1 = (const float*)d_in[1];
    const float* b1 = (const float*)d_in[2];
    const float* W2 = (const float*)d_in[3];
    const float* b2 = (const float*)d_in[4];
    const float* W3 = (const float*)d_in[5];
    const float* b3 = (const float*)d_in[6];
    float* out = (float*)d_out;

    cudaFuncSetAttribute(ecg_fused, cudaFuncAttributeMaxDynamicSharedMemorySize, SMEM_BYTES);
    ecg_fused<<<BATCH / BT, THREADS, SMEM_BYTES>>>(x, W1, b1, W2, b2, W3, b3, out);
}

// round 5
// speedup vs baseline: 1.1020x; 1.1020x over previous
#include <cuda_runtime.h>

typedef unsigned long long u64;
#define DEV __device__ __forceinline__

DEV u64 pk2(float v) {
    u64 r; asm("mov.b64 %0, {%1, %1};" : "=l"(r) : "f"(v)); return r;
}
DEV void fma2(u64& d, u64 a, u64 b) {
    asm("fma.rn.f32x2 %0, %1, %2, %0;" : "+l"(d) : "l"(a), "l"(b));
}
DEV void upk2(u64 v, float& lo, float& hi) {
    asm("mov.b64 {%0, %1}, %2;" : "=f"(lo), "=f"(hi) : "l"(v));
}

constexpr int BATCH = 16384;
constexpr int F1    = 512;
constexpr int HID   = 256;
constexpr int NOUT  = 128;
constexpr int BT    = 4;      // batch elements per CTA
constexpr int MT    = 48;     // rows per CTA
constexpr int KB    = 16;     // k-slice
constexpr int THREADS = 256;
constexpr int ASTR  = 52;     // transposed activation plane stride (48 rows + pad)

constexpr int HT_ELEMS = HID * ASTR;       // 13312 (k-major activations, in-place mix)
constexpr int WS_ELEMS = 2 * KB * HID;     // 8192  (weight double buffer)
constexpr int XT_ELEMS = 2 * KB * ASTR;    // 1664  (layer-1 x slices, transposed, dbl buf)
constexpr int A_ELEMS  = 144;
constexpr int SMEM_BYTES = (HT_ELEMS + WS_ELEMS + XT_ELEMS + A_ELEMS + 16) * 4;  // ~93KB

// Fixed ECG graph neighbor lists (incl. self), 42 nonzeros of the 12x12 A_norm.
__device__ constexpr int NBR_OFF[13] = {0,5,11,16,20,23,26,28,31,34,37,40,42};
__device__ constexpr int NBR[42] = {
    0,1,2,3,4,
    0,1,2,3,4,5,
    0,1,2,3,5,
    0,1,2,3,
    0,1,4,
    1,2,5,
    6,7,
    6,7,8,
    7,8,9,
    8,9,10,
    9,10,11,
    10,11
};

// In-place A-mix on transposed buffer HT[col][12b..12b+11]; optional fused epilogue.
// Each task reads/writes ONLY its own 12-float segment -> no intra-phase sync needed.
template<int NCOL, bool RELU, bool FINAL>
DEV void mix_phase(float* HT, const float* Am, const float* __restrict__ bias,
                   float* __restrict__ out, long long obase, int tid)
{
    constexpr int NT = NCOL * BT / THREADS;   // tasks per thread
    #pragma unroll
    for (int s = 0; s < NT; s++) {
        int t   = tid + s * THREADS;
        int b   = t & (BT - 1);
        int col = t >> 2;
        float* hp = HT + col * ASTR + b * 12;
        float4 h0 = *(const float4*)(hp);
        float4 h1 = *(const float4*)(hp + 4);
        float4 h2 = *(const float4*)(hp + 8);
        float h[12] = {h0.x,h0.y,h0.z,h0.w, h1.x,h1.y,h1.z,h1.w, h2.x,h2.y,h2.z,h2.w};
        float bv = __ldg(bias + col);
        float y[12];
        #pragma unroll
        for (int l = 0; l < 12; l++) {
            float acc = 0.f;
            #pragma unroll
            for (int q = NBR_OFF[l]; q < NBR_OFF[l + 1]; q++) {
                int m = NBR[q];
                acc += Am[l * 12 + m] * h[m];
            }
            y[l] = acc + bv;
            if (RELU) y[l] = fmaxf(y[l], 0.f);
        }
        if (!FINAL) {
            *(float4*)(hp)     = make_float4(y[0], y[1], y[2],  y[3]);
            *(float4*)(hp + 4) = make_float4(y[4], y[5], y[6],  y[7]);
            *(float4*)(hp + 8) = make_float4(y[8], y[9], y[10], y[11]);
        } else {
            float sum = 0.f, mx = -3.402823466e38f;
            #pragma unroll
            for (int l = 0; l < 12; l++) { sum += y[l]; mx = fmaxf(mx, y[l]); }
            float* op = out + (obase + b) * (2 * NOUT);
            op[col]        = sum * (1.0f / 12.0f);
            op[NOUT + col] = mx;
        }
    }
}

__global__ void __launch_bounds__(THREADS, 2)
ecg_fused(const float* __restrict__ x,
          const float* __restrict__ W1, const float* __restrict__ b1,
          const float* __restrict__ W2, const float* __restrict__ b2,
          const float* __restrict__ W3, const float* __restrict__ b3,
          float* __restrict__ out)
{
    extern __shared__ float sm[];
    float* HT  = sm;                  // [HID][ASTR] transposed activations
    float* Wsb = sm + HT_ELEMS;       // weight slices, double buffered
    float* XT  = Wsb + WS_ELEMS;      // layer-1 x slices, transposed, double buffered
    float* Am  = XT + XT_ELEMS;       // 12x12 normalized adjacency

    const int tid  = threadIdx.x;
    const int lane = tid & 31;
    const int w    = tid >> 5;        // 0..7
    // R2 warp microstructure: 16 row-threads x 2 col-threads (warp tile 48x32)
    const int tx   = lane & 1;        // 2 col sub-groups in warp
    const int tyl  = lane >> 1;       // 16 row threads in warp
    const int r0   = tyl * 3;                     // 3 rows, covers all 48
    const int c0   = w * 32 + tx * 16;            // 16 cols (N=256 layers)
    const int c0_3 = w * 16 + tx * 8;             // 8 cols  (N=128 layer)
    const long long rowbase = (long long)blockIdx.x * MT;
    const long long obase   = (long long)blockIdx.x * BT;

    // Build A_norm once per CTA: adj + 2*I (buffer eye + PyG self-loop), sym-normalized.
    if (tid == 0) {
        float a[12][12];
        for (int i = 0; i < 12; i++)
            for (int j = 0; j < 12; j++) a[i][j] = (i == j) ? 2.0f : 0.0f;
        const int ei[15] = {0,0,1,0,1,2,0,1,1,2,6,7,8,9,10};
        const int ej[15] = {1,2,2,3,3,3,4,4,5,5,7,8,9,10,11};
        for (int e = 0; e < 15; e++) { a[ei[e]][ej[e]] = 1.0f; a[ej[e]][ei[e]] = 1.0f; }
        float dinv[12];
        for (int i = 0; i < 12; i++) {
            float s = 0.f;
            for (int j = 0; j < 12; j++) s += a[i][j];
            dinv[i] = 1.0f / sqrtf(s);
        }
        for (int i = 0; i < 12; i++)
            for (int j = 0; j < 12; j++)
                Am[i * 12 + j] = dinv[i] * a[i][j] * dinv[j];
    }

    // staging assignments
    const int wk  = tid >> 4;            // 0..15 k within weight slice
    const int wn  = (tid & 15) << 4;     // 0..240 (16 floats per thread, N=256)
    const int wn3 = (tid & 15) << 3;     // 0..120 (8 floats per thread, N=128)
    const int xr  = tid >> 2;            // 0..63, active <48
    const int xc  = (tid & 3) << 2;      // 0,4,8,12
    const bool xact = tid < (MT * 4);    // 192 threads

    // ================= Layer 1: P = X(48x512) @ W1(512x256) =================
    u64 acc[3][8];
    #pragma unroll
    for (int i = 0; i < 3; i++)
        #pragma unroll
        for (int j = 0; j < 8; j++) acc[i][j] = 0ull;

    {
        #pragma unroll
        for (int v = 0; v < 4; v++) {
            float4 wv = *(const float4*)(W1 + (size_t)wk * HID + wn + v * 4);
            *(float4*)(Wsb + wk * HID + wn + v * 4) = wv;
        }
        if (xact) {
            float4 xv = *(const float4*)(x + (rowbase + xr) * F1 + xc);
            XT[(xc + 0) * ASTR + xr] = xv.x;
            XT[(xc + 1) * ASTR + xr] = xv.y;
            XT[(xc + 2) * ASTR + xr] = xv.z;
            XT[(xc + 3) * ASTR + xr] = xv.w;
        }
    }
    __syncthreads();

    for (int kb = 0; kb < F1; kb += KB) {
        const int cur = (kb / KB) & 1;
        const int nxt = cur ^ 1;
        float4 nw[4], nx;
        const bool more = (kb + KB) < F1;
        if (more) {
            #pragma unroll
            for (int v = 0; v < 4; v++)
                nw[v] = *(const float4*)(W1 + (size_t)(kb + KB + wk) * HID + wn + v * 4);
            if (xact) nx = *(const float4*)(x + (rowbase + xr) * F1 + kb + KB + xc);
        }
        const float* Wc = Wsb + cur * KB * HID;
        const float* Ac = XT + cur * KB * ASTR;
        #pragma unroll
        for (int k = 0; k < KB; k++) {
            u64 a0 = pk2(Ac[k * ASTR + r0 + 0]);
            u64 a1 = pk2(Ac[k * ASTR + r0 + 1]);
            u64 a2 = pk2(Ac[k * ASTR + r0 + 2]);
            #pragma unroll
            for (int j = 0; j < 4; j++) {
                ulonglong2 wv = *(const ulonglong2*)(Wc + k * HID + c0 + (j << 2));
                fma2(acc[0][2*j],   a0, wv.x); fma2(acc[0][2*j+1], a0, wv.y);
                fma2(acc[1][2*j],   a1, wv.x); fma2(acc[1][2*j+1], a1, wv.y);
                fma2(acc[2][2*j],   a2, wv.x); fma2(acc[2][2*j+1], a2, wv.y);
            }
        }
        if (more) {
            #pragma unroll
            for (int v = 0; v < 4; v++)
                *(float4*)(Wsb + nxt * KB * HID + wk * HID + wn + v * 4) = nw[v];
            if (xact) {
                float* xd = XT + nxt * KB * ASTR;
                xd[(xc + 0) * ASTR + xr] = nx.x;
                xd[(xc + 1) * ASTR + xr] = nx.y;
                xd[(xc + 2) * ASTR + xr] = nx.z;
                xd[(xc + 3) * ASTR + xr] = nx.w;
            }
        }
        __syncthreads();
    }

    // P1 -> HT (transposed). acc[i][jj] = cols c0 + 4*(jj>>1) + 2*(jj&1) + {0,1}
    #pragma unroll
    for (int i = 0; i < 3; i++)
        #pragma unroll
        for (int jj = 0; jj < 8; jj++) {
            int col = c0 + ((jj >> 1) << 2) + ((jj & 1) << 1);
            float lo, hi; upk2(acc[i][jj], lo, hi);
            HT[col * ASTR + r0 + i]       = lo;
            HT[(col + 1) * ASTR + r0 + i] = hi;
        }
    __syncthreads();
    mix_phase<HID, true, false>(HT, Am, b1, out, obase, tid);
    __syncthreads();

    // ================= Layer 2: P = H1(48x256) @ W2(256x256) =================
    #pragma unroll
    for (int i = 0; i < 3; i++)
        #pragma unroll
        for (int j = 0; j < 8; j++) acc[i][j] = 0ull;

    {
        #pragma unroll
        for (int v = 0; v < 4; v++) {
            float4 wv = *(const float4*)(W2 + (size_t)wk * HID + wn + v * 4);
            *(float4*)(Wsb + wk * HID + wn + v * 4) = wv;
        }
    }
    __syncthreads();

    for (int kb = 0; kb < HID; kb += KB) {
        const int cur = (kb / KB) & 1;
        const int nxt = cur ^ 1;
        float4 nw[4];
        const bool more = (kb + KB) < HID;
        if (more) {
            #pragma unroll
            for (int v = 0; v < 4; v++)
                nw[v] = *(const float4*)(W2 + (size_t)(kb + KB + wk) * HID + wn + v * 4);
        }
        const float* Wc = Wsb + cur * KB * HID;
        const float* Ac = HT + kb * ASTR;
        #pragma unroll
        for (int k = 0; k < KB; k++) {
            u64 a0 = pk2(Ac[k * ASTR + r0 + 0]);
            u64 a1 = pk2(Ac[k * ASTR + r0 + 1]);
            u64 a2 = pk2(Ac[k * ASTR + r0 + 2]);
            #pragma unroll
            for (int j = 0; j < 4; j++) {
                ulonglong2 wv = *(const ulonglong2*)(Wc + k * HID + c0 + (j << 2));
                fma2(acc[0][2*j],   a0, wv.x); fma2(acc[0][2*j+1], a0, wv.y);
                fma2(acc[1][2*j],   a1, wv.x); fma2(acc[1][2*j+1], a1, wv.y);
                fma2(acc[2][2*j],   a2, wv.x); fma2(acc[2][2*j+1], a2, wv.y);
            }
        }
        if (more) {
            #pragma unroll
            for (int v = 0; v < 4; v++)
                *(float4*)(Wsb + nxt * KB * HID + wk * HID + wn + v * 4) = nw[v];
        }
        __syncthreads();
    }

    #pragma unroll
    for (int i = 0; i < 3; i++)
        #pragma unroll
        for (int jj = 0; jj < 8; jj++) {
            int col = c0 + ((jj >> 1) << 2) + ((jj & 1) << 1);
            float lo, hi; upk2(acc[i][jj], lo, hi);
            HT[col * ASTR + r0 + i]       = lo;
            HT[(col + 1) * ASTR + r0 + i] = hi;
        }
    __syncthreads();
    mix_phase<HID, true, false>(HT, Am, b2, out, obase, tid);
    __syncthreads();

    // ================= Layer 3: P = H2(48x256) @ W3(256x128) =================
    u64 acc3[3][4];
    #pragma unroll
    for (int i = 0; i < 3; i++)
        #pragma unroll
        for (int j = 0; j < 4; j++) acc3[i][j] = 0ull;

    {
        #pragma unroll
        for (int v = 0; v < 2; v++) {
            float4 wv = *(const float4*)(W3 + (size_t)wk * NOUT + wn3 + v * 4);
            *(float4*)(Wsb + wk * NOUT + wn3 + v * 4) = wv;
        }
    }
    __syncthreads();

    for (int kb = 0; kb < HID; kb += KB) {
        const int cur = (kb / KB) & 1;
        const int nxt = cur ^ 1;
        float4 nw[2];
        const bool more = (kb + KB) < HID;
        if (more) {
            #pragma unroll
            for (int v = 0; v < 2; v++)
                nw[v] = *(const float4*)(W3 + (size_t)(kb + KB + wk) * NOUT + wn3 + v * 4);
        }
        const float* Wc = Wsb + cur * KB * NOUT;
        const float* Ac = HT + kb * ASTR;
        #pragma unroll
        for (int k = 0; k < KB; k++) {
            u64 a0 = pk2(Ac[k * ASTR + r0 + 0]);
            u64 a1 = pk2(Ac[k * ASTR + r0 + 1]);
            u64 a2 = pk2(Ac[k * ASTR + r0 + 2]);
            #pragma unroll
            for (int j = 0; j < 2; j++) {
                ulonglong2 wv = *(const ulonglong2*)(Wc + k * NOUT + c0_3 + (j << 2));
                fma2(acc3[0][2*j],   a0, wv.x); fma2(acc3[0][2*j+1], a0, wv.y);
                fma2(acc3[1][2*j],   a1, wv.x); fma2(acc3[1][2*j+1], a1, wv.y);
                fma2(acc3[2][2*j],   a2, wv.x); fma2(acc3[2][2*j+1], a2, wv.y);
            }
        }
        if (more) {
            #pragma unroll
            for (int v = 0; v < 2; v++)
                *(float4*)(Wsb + nxt * KB * NOUT + wk * NOUT + wn3 + v * 4) = nw[v];
        }
        __syncthreads();
    }

    #pragma unroll
    for (int i = 0; i < 3; i++)
        #pragma unroll
        for (int jj = 0; jj < 4; jj++) {
            int col = c0_3 + ((jj >> 1) << 2) + ((jj & 1) << 1);
            float lo, hi; upk2(acc3[i][jj], lo, hi);
            HT[col * ASTR + r0 + i]       = lo;
            HT[(col + 1) * ASTR + r0 + i] = hi;
        }
    __syncthreads();
    // final mix fused with mean/max epilogue, writes global out
    mix_phase<NOUT, false, true>(HT, Am, b3, out, obase, tid);
}

extern "C" void kernel_launch(void* const* d_in, const int* in_sizes, int n_in,
                              void* d_out, int out_size)
{
    const float* x  = (const float*)d_in[0];
    const float* W1 = (const float*)d_in[1];
    const float* b1 = (const float*)d_in[2];
    const float* W2 = (const float*)d_in[3];
    const float* b2 = (const float*)d_in[4];
    const float* W3 = (const float*)d_in[5];
    const float* b3 = (const float*)d_in[6];
    float* out = (float*)d_out;

    cudaFuncSetAttribute(ecg_fused, cudaFuncAttributeMaxDynamicSharedMemorySize, SMEM_BYTES);
    ecg_fused<<<BATCH / BT, THREADS, SMEM_BYTES>>>(x, W1, b1, W2, b2, W3, b3, out);
}

// round 6
// speedup vs baseline: 2.1247x; 1.9280x over previous
#include <cuda_runtime.h>
#include <cstdint>

typedef unsigned long long u64;
#define DEV __device__ __forceinline__

DEV u64 pk2(float v) {
    u64 r; asm("mov.b64 %0, {%1, %1};" : "=l"(r) : "f"(v)); return r;
}
DEV void fma2(u64& d, u64 a, u64 b) {
    asm("fma.rn.f32x2 %0, %1, %2, %0;" : "+l"(d) : "l"(a), "l"(b));
}
DEV void upk2(u64 v, float& lo, float& hi) {
    asm("mov.b64 {%0, %1}, %2;" : "=f"(lo), "=f"(hi) : "l"(v));
}
DEV void cpa16(uint32_t s, const void* g) {
    asm volatile("cp.async.cg.shared.global [%0], [%1], 16;" :: "r"(s), "l"(g));
}
DEV void cpa_commit() { asm volatile("cp.async.commit_group;"); }
DEV void cpa_wait0()  { asm volatile("cp.async.wait_group 0;"); }

constexpr int BATCH = 16384;
constexpr int F1    = 512;
constexpr int HID   = 256;
constexpr int NOUT  = 128;
constexpr int BT    = 8;      // batch elements per CTA
constexpr int MT    = 96;     // rows per CTA
constexpr int KB    = 32;     // k-slice (doubled vs R2)
constexpr int THREADS = 512;
constexpr int ASTR  = 100;    // transposed activation plane stride (96 rows + pad)

constexpr int HT_ELEMS = HID * ASTR;       // 25600
constexpr int WS_ELEMS = 2 * KB * HID;     // 16384 (weight double buffer, 32k-slices)
constexpr int XT_ELEMS = 2 * KB * ASTR;    // 6400  (layer-1 x slices, transposed, dbl buf)
constexpr int A_ELEMS  = 144;
constexpr int SMEM_BYTES = (HT_ELEMS + WS_ELEMS + XT_ELEMS + A_ELEMS + 16) * 4; // ~194KB

// Fixed ECG graph neighbor lists (incl. self), 42 nonzeros of the 12x12 A_norm.
__device__ constexpr int NBR_OFF[13] = {0,5,11,16,20,23,26,28,31,34,37,40,42};
__device__ constexpr int NBR[42] = {
    0,1,2,3,4,
    0,1,2,3,4,5,
    0,1,2,3,5,
    0,1,2,3,
    0,1,4,
    1,2,5,
    6,7,
    6,7,8,
    7,8,9,
    8,9,10,
    9,10,11,
    10,11
};

// In-place A-mix on transposed buffer HT[col][12b..12b+11]; optional fused epilogue.
// Each task reads/writes ONLY its own 12-float segment -> no intra-phase sync needed.
template<int NCOL, bool RELU, bool FINAL>
DEV void mix_phase(float* HT, const float* Am, const float* __restrict__ bias,
                   float* __restrict__ out, long long obase, int tid)
{
    constexpr int NT = NCOL * BT / THREADS;   // tasks per thread
    #pragma unroll
    for (int s = 0; s < NT; s++) {
        int t   = tid + s * THREADS;
        int b   = t & 7;
        int col = t >> 3;
        float* hp = HT + col * ASTR + b * 12;
        float4 h0 = *(const float4*)(hp);
        float4 h1 = *(const float4*)(hp + 4);
        float4 h2 = *(const float4*)(hp + 8);
        float h[12] = {h0.x,h0.y,h0.z,h0.w, h1.x,h1.y,h1.z,h1.w, h2.x,h2.y,h2.z,h2.w};
        float bv = __ldg(bias + col);
        float y[12];
        #pragma unroll
        for (int l = 0; l < 12; l++) {
            float acc = 0.f;
            #pragma unroll
            for (int q = NBR_OFF[l]; q < NBR_OFF[l + 1]; q++) {
                int m = NBR[q];
                acc += Am[l * 12 + m] * h[m];
            }
            y[l] = acc + bv;
            if (RELU) y[l] = fmaxf(y[l], 0.f);
        }
        if (!FINAL) {
            *(float4*)(hp)     = make_float4(y[0], y[1], y[2],  y[3]);
            *(float4*)(hp + 4) = make_float4(y[4], y[5], y[6],  y[7]);
            *(float4*)(hp + 8) = make_float4(y[8], y[9], y[10], y[11]);
        } else {
            float sum = 0.f, mx = -3.402823466e38f;
            #pragma unroll
            for (int l = 0; l < 12; l++) { sum += y[l]; mx = fmaxf(mx, y[l]); }
            float* op = out + (obase + b) * (2 * NOUT);
            op[col]        = sum * (1.0f / 12.0f);
            op[NOUT + col] = mx;
        }
    }
}

__global__ void __launch_bounds__(THREADS, 1)
ecg_fused(const float* __restrict__ x,
          const float* __restrict__ W1, const float* __restrict__ b1,
          const float* __restrict__ W2, const float* __restrict__ b2,
          const float* __restrict__ W3, const float* __restrict__ b3,
          float* __restrict__ out)
{
    extern __shared__ float sm[];
    float* HT  = sm;                  // [HID][ASTR] transposed activations
    float* Wsb = sm + HT_ELEMS;       // weight slices, double buffered
    float* XT  = Wsb + WS_ELEMS;      // layer-1 x slices, transposed, double buffered
    float* Am  = XT + XT_ELEMS;       // 12x12 normalized adjacency

    const uint32_t wsb_u = (uint32_t)__cvta_generic_to_shared(Wsb);

    const int tid  = threadIdx.x;
    const int lane = tid & 31;
    const int w    = tid >> 5;        // 0..15
    const int tx   = lane & 1;        // 2 col sub-groups in warp
    const int tyl  = lane >> 1;       // 16 row threads in warp
    const int rg   = w & 1;           // row group (0..1)
    const int cg   = w >> 1;          // col group (0..7)
    const int r0   = rg * 48 + tyl * 3;           // 3 rows
    const int c0   = cg * 32 + tx * 16;           // 16 cols (N=256 layers)
    const int c0_3 = cg * 16 + tx * 8;            // 8 cols  (N=128 layer)
    const long long rowbase = (long long)blockIdx.x * MT;
    const long long obase   = (long long)blockIdx.x * BT;

    // Build A_norm once per CTA: adj + 2*I (buffer eye + PyG self-loop), sym-normalized.
    if (tid == 0) {
        float a[12][12];
        for (int i = 0; i < 12; i++)
            for (int j = 0; j < 12; j++) a[i][j] = (i == j) ? 2.0f : 0.0f;
        const int ei[15] = {0,0,1,0,1,2,0,1,1,2,6,7,8,9,10};
        const int ej[15] = {1,2,2,3,3,3,4,4,5,5,7,8,9,10,11};
        for (int e = 0; e < 15; e++) { a[ei[e]][ej[e]] = 1.0f; a[ej[e]][ei[e]] = 1.0f; }
        float dinv[12];
        for (int i = 0; i < 12; i++) {
            float s = 0.f;
            for (int j = 0; j < 12; j++) s += a[i][j];
            dinv[i] = 1.0f / sqrtf(s);
        }
        for (int i = 0; i < 12; i++)
            for (int j = 0; j < 12; j++)
                Am[i * 12 + j] = dinv[i] * a[i][j] * dinv[j];
    }

    // Weight staging (cp.async): slice = KB x N.
    // N=256: 512 threads, 16 floats each: row wk2 = tid>>4 (0..31), cols wn2..wn2+15.
    const int wk2 = tid >> 4;            // 0..31
    const int wn2 = (tid & 15) << 4;     // 0..240
    // N=128: 8 floats each: row wk2, cols wn3t..wn3t+7.
    const int wn3t = (tid & 15) << 3;    // 0..120
    // X staging (registers->transposed STS): 96 rows x 4 thr/row, 8 k each.
    const int xr  = tid >> 2;            // 0..127, active <96
    const int xc  = (tid & 3) << 3;      // 0,8,16,24
    const bool xact = tid < (MT * 4);    // 384 threads

    // smem byte offsets for weight cp.async destinations
    const uint32_t wdst0 = wsb_u + (uint32_t)(wk2 * HID + wn2) * 4u;       // N=256 buf0
    const uint32_t wdst3 = wsb_u + (uint32_t)(wk2 * NOUT + wn3t) * 4u;     // N=128 buf0
    constexpr uint32_t WBUF = KB * HID * 4;       // bytes per N=256 buffer
    constexpr uint32_t WBUF3 = KB * NOUT * 4;     // bytes per N=128 buffer

    // ================= Layer 1: P = X(96x512) @ W1(512x256) =================
    u64 acc[3][8];
    #pragma unroll
    for (int i = 0; i < 3; i++)
        #pragma unroll
        for (int j = 0; j < 8; j++) acc[i][j] = 0ull;

    {
        // preload slice 0: weights via cp.async, X via regs->transposed STS
        #pragma unroll
        for (int v = 0; v < 4; v++)
            cpa16(wdst0 + v * 16, W1 + (size_t)wk2 * HID + wn2 + v * 4);
        cpa_commit();
        if (xact) {
            float4 xa = *(const float4*)(x + (rowbase + xr) * F1 + xc);
            float4 xb = *(const float4*)(x + (rowbase + xr) * F1 + xc + 4);
            XT[(xc + 0) * ASTR + xr] = xa.x;
            XT[(xc + 1) * ASTR + xr] = xa.y;
            XT[(xc + 2) * ASTR + xr] = xa.z;
            XT[(xc + 3) * ASTR + xr] = xa.w;
            XT[(xc + 4) * ASTR + xr] = xb.x;
            XT[(xc + 5) * ASTR + xr] = xb.y;
            XT[(xc + 6) * ASTR + xr] = xb.z;
            XT[(xc + 7) * ASTR + xr] = xb.w;
        }
        cpa_wait0();
    }
    __syncthreads();

    for (int kb = 0; kb < F1; kb += KB) {
        const int cur = (kb / KB) & 1;
        const int nxt = cur ^ 1;
        const bool more = (kb + KB) < F1;
        float4 nxa, nxb;
        if (more) {
            #pragma unroll
            for (int v = 0; v < 4; v++)
                cpa16(wdst0 + nxt * WBUF + v * 16,
                      W1 + (size_t)(kb + KB + wk2) * HID + wn2 + v * 4);
            cpa_commit();
            if (xact) {
                nxa = *(const float4*)(x + (rowbase + xr) * F1 + kb + KB + xc);
                nxb = *(const float4*)(x + (rowbase + xr) * F1 + kb + KB + xc + 4);
            }
        }
        const float* Wc = Wsb + cur * KB * HID;
        const float* Ac = XT + cur * KB * ASTR;
        #pragma unroll
        for (int k = 0; k < KB; k++) {
            u64 a0 = pk2(Ac[k * ASTR + r0 + 0]);
            u64 a1 = pk2(Ac[k * ASTR + r0 + 1]);
            u64 a2 = pk2(Ac[k * ASTR + r0 + 2]);
            #pragma unroll
            for (int j = 0; j < 4; j++) {
                ulonglong2 wv = *(const ulonglong2*)(Wc + k * HID + c0 + (j << 2));
                fma2(acc[0][2*j],   a0, wv.x); fma2(acc[0][2*j+1], a0, wv.y);
                fma2(acc[1][2*j],   a1, wv.x); fma2(acc[1][2*j+1], a1, wv.y);
                fma2(acc[2][2*j],   a2, wv.x); fma2(acc[2][2*j+1], a2, wv.y);
            }
        }
        if (more) {
            if (xact) {
                float* xd = XT + nxt * KB * ASTR;
                xd[(xc + 0) * ASTR + xr] = nxa.x;
                xd[(xc + 1) * ASTR + xr] = nxa.y;
                xd[(xc + 2) * ASTR + xr] = nxa.z;
                xd[(xc + 3) * ASTR + xr] = nxa.w;
                xd[(xc + 4) * ASTR + xr] = nxb.x;
                xd[(xc + 5) * ASTR + xr] = nxb.y;
                xd[(xc + 6) * ASTR + xr] = nxb.z;
                xd[(xc + 7) * ASTR + xr] = nxb.w;
            }
            cpa_wait0();
        }
        __syncthreads();
    }

    // P1 -> HT (transposed). acc[i][jj] = cols c0 + 4*(jj>>1) + 2*(jj&1) + {0,1}
    #pragma unroll
    for (int i = 0; i < 3; i++)
        #pragma unroll
        for (int jj = 0; jj < 8; jj++) {
            int col = c0 + ((jj >> 1) << 2) + ((jj & 1) << 1);
            float lo, hi; upk2(acc[i][jj], lo, hi);
            HT[col * ASTR + r0 + i]       = lo;
            HT[(col + 1) * ASTR + r0 + i] = hi;
        }
    __syncthreads();
    mix_phase<HID, true, false>(HT, Am, b1, out, obase, tid);
    __syncthreads();

    // ================= Layer 2: P = H1(96x256) @ W2(256x256) =================
    #pragma unroll
    for (int i = 0; i < 3; i++)
        #pragma unroll
        for (int j = 0; j < 8; j++) acc[i][j] = 0ull;

    {
        #pragma unroll
        for (int v = 0; v < 4; v++)
            cpa16(wdst0 + v * 16, W2 + (size_t)wk2 * HID + wn2 + v * 4);
        cpa_commit();
        cpa_wait0();
    }
    __syncthreads();

    for (int kb = 0; kb < HID; kb += KB) {
        const int cur = (kb / KB) & 1;
        const int nxt = cur ^ 1;
        const bool more = (kb + KB) < HID;
        if (more) {
            #pragma unroll
            for (int v = 0; v < 4; v++)
                cpa16(wdst0 + nxt * WBUF + v * 16,
                      W2 + (size_t)(kb + KB + wk2) * HID + wn2 + v * 4);
            cpa_commit();
        }
        const float* Wc = Wsb + cur * KB * HID;
        const float* Ac = HT + kb * ASTR;
        #pragma unroll
        for (int k = 0; k < KB; k++) {
            u64 a0 = pk2(Ac[k * ASTR + r0 + 0]);
            u64 a1 = pk2(Ac[k * ASTR + r0 + 1]);
            u64 a2 = pk2(Ac[k * ASTR + r0 + 2]);
            #pragma unroll
            for (int j = 0; j < 4; j++) {
                ulonglong2 wv = *(const ulonglong2*)(Wc + k * HID + c0 + (j << 2));
                fma2(acc[0][2*j],   a0, wv.x); fma2(acc[0][2*j+1], a0, wv.y);
                fma2(acc[1][2*j],   a1, wv.x); fma2(acc[1][2*j+1], a1, wv.y);
                fma2(acc[2][2*j],   a2, wv.x); fma2(acc[2][2*j+1], a2, wv.y);
            }
        }
        if (more) cpa_wait0();
        __syncthreads();
    }

    #pragma unroll
    for (int i = 0; i < 3; i++)
        #pragma unroll
        for (int jj = 0; jj < 8; jj++) {
            int col = c0 + ((jj >> 1) << 2) + ((jj & 1) << 1);
            float lo, hi; upk2(acc[i][jj], lo, hi);
            HT[col * ASTR + r0 + i]       = lo;
            HT[(col + 1) * ASTR + r0 + i] = hi;
        }
    __syncthreads();
    mix_phase<HID, true, false>(HT, Am, b2, out, obase, tid);
    __syncthreads();

    // ================= Layer 3: P = H2(96x256) @ W3(256x128) =================
    u64 acc3[3][4];
    #pragma unroll
    for (int i = 0; i < 3; i++)
        #pragma unroll
        for (int j = 0; j < 4; j++) acc3[i][j] = 0ull;

    {
        #pragma unroll
        for (int v = 0; v < 2; v++)
            cpa16(wdst3 + v * 16, W3 + (size_t)wk2 * NOUT + wn3t + v * 4);
        cpa_commit();
        cpa_wait0();
    }
    __syncthreads();

    for (int kb = 0; kb < HID; kb += KB) {
        const int cur = (kb / KB) & 1;
        const int nxt = cur ^ 1;
        const bool more = (kb + KB) < HID;
        if (more) {
            #pragma unroll
            for (int v = 0; v < 2; v++)
                cpa16(wdst3 + nxt * WBUF3 + v * 16,
                      W3 + (size_t)(kb + KB + wk2) * NOUT + wn3t + v * 4);
            cpa_commit();
        }
        const float* Wc = Wsb + cur * KB * NOUT;
        const float* Ac = HT + kb * ASTR;
        #pragma unroll
        for (int k = 0; k < KB; k++) {
            u64 a0 = pk2(Ac[k * ASTR + r0 + 0]);
            u64 a1 = pk2(Ac[k * ASTR + r0 + 1]);
            u64 a2 = pk2(Ac[k * ASTR + r0 + 2]);
            #pragma unroll
            for (int j = 0; j < 2; j++) {
                ulonglong2 wv = *(const ulonglong2*)(Wc + k * NOUT + c0_3 + (j << 2));
                fma2(acc3[0][2*j],   a0, wv.x); fma2(acc3[0][2*j+1], a0, wv.y);
                fma2(acc3[1][2*j],   a1, wv.x); fma2(acc3[1][2*j+1], a1, wv.y);
                fma2(acc3[2][2*j],   a2, wv.x); fma2(acc3[2][2*j+1], a2, wv.y);
            }
        }
        if (more) cpa_wait0();
        __syncthreads();
    }

    #pragma unroll
    for (int i = 0; i < 3; i++)
        #pragma unroll
        for (int jj = 0; jj < 4; jj++) {
            int col = c0_3 + ((jj >> 1) << 2) + ((jj & 1) << 1);
            float lo, hi; upk2(acc3[i][jj], lo, hi);
            HT[col * ASTR + r0 + i]       = lo;
            HT[(col + 1) * ASTR + r0 + i] = hi;
        }
    __syncthreads();
    // final mix fused with mean/max epilogue, writes global out
    mix_phase<NOUT, false, true>(HT, Am, b3, out, obase, tid);
}

extern "C" void kernel_launch(void* const* d_in, const int* in_sizes, int n_in,
                              void* d_out, int out_size)
{
    const float* x  = (const float*)d_in[0];
    const float* W1 = (const float*)d_in[1];
    const float* b1 = (const float*)d_in[2];
    const float* W2 = (const float*)d_in[3];
    const float* b2 = (const float*)d_in[4];
    const float* W3 = (const float*)d_in[5];
    const float* b3 = (const float*)d_in[6];
    float* out = (float*)d_out;

    cudaFuncSetAttribute(ecg_fused, cudaFuncAttributeMaxDynamicSharedMemorySize, SMEM_BYTES);
    ecg_fused<<<BATCH / BT, THREADS, SMEM_BYTES>>>(x, W1, b1, W2, b2, W3, b3, out);
}

// round 8
// speedup vs baseline: 3.6515x; 1.7186x over previous
#include <cuda_runtime.h>
#include <cstdint>

typedef unsigned long long u64;
typedef unsigned int u32;
typedef unsigned short u16;
#define DEV __device__ __forceinline__

// ---------------- global scratch: split + transposed bf16 weight planes [N][K] ----------------
__device__ __align__(256) u16 g_w1h[256 * 512];
__device__ __align__(256) u16 g_w1l[256 * 512];
__device__ __align__(256) u16 g_w2h[256 * 256];
__device__ __align__(256) u16 g_w2l[256 * 256];
__device__ __align__(256) u16 g_w3h[128 * 256];
__device__ __align__(256) u16 g_w3l[128 * 256];

// ================= PTX helpers (base ISA only, no tcgen05) =================
DEV void cpa16(u32 s, const void* g) {
    asm volatile("cp.async.cg.shared.global [%0], [%1], 16;" :: "r"(s), "l"(g));
}
DEV void cpa_commit() { asm volatile("cp.async.commit_group;"); }
DEV void cpa_wait0()  { asm volatile("cp.async.wait_group 0;"); }

DEV u32 pack_bf16(float lo, float hi) {
    u32 r; asm("cvt.rn.bf16x2.f32 %0, %1, %2;" : "=r"(r) : "f"(hi), "f"(lo)); return r;
}
DEV float bf2f(u16 u) { float f; asm("cvt.f32.bf16 %0, %1;" : "=f"(f) : "h"(u)); return f; }

DEV void mma16816(float* d, u32 a0, u32 a1, u32 a2, u32 a3, u32 b0, u32 b1) {
    asm volatile(
        "mma.sync.aligned.m16n8k16.row.col.f32.bf16.bf16.f32 "
        "{%0,%1,%2,%3}, {%4,%5,%6,%7}, {%8,%9}, {%0,%1,%2,%3};"
        : "+f"(d[0]), "+f"(d[1]), "+f"(d[2]), "+f"(d[3])
        : "r"(a0), "r"(a1), "r"(a2), "r"(a3), "r"(b0), "r"(b1));
}

// ================= weight split + transpose pre-kernel =================
__global__ void conv_w(const float* __restrict__ W1, const float* __restrict__ W2,
                       const float* __restrict__ W3)
{
    int idx = blockIdx.x * blockDim.x + threadIdx.x;
    int stride = gridDim.x * blockDim.x;
    for (int i = idx; i < 512 * 256; i += stride) {
        int k = i >> 8, n = i & 255;
        float v = W1[i];
        u16 h; asm("cvt.rn.bf16.f32 %0, %1;" : "=h"(h) : "f"(v));
        float hf = bf2f(h);
        u16 l; asm("cvt.rn.bf16.f32 %0, %1;" : "=h"(l) : "f"(v - hf));
        g_w1h[n * 512 + k] = h;
        g_w1l[n * 512 + k] = l;
    }
    for (int i = idx; i < 256 * 256; i += stride) {
        int k = i >> 8, n = i & 255;
        float v = W2[i];
        u16 h; asm("cvt.rn.bf16.f32 %0, %1;" : "=h"(h) : "f"(v));
        float hf = bf2f(h);
        u16 l; asm("cvt.rn.bf16.f32 %0, %1;" : "=h"(l) : "f"(v - hf));
        g_w2h[n * 256 + k] = h;
        g_w2l[n * 256 + k] = l;
    }
    for (int i = idx; i < 256 * 128; i += stride) {
        int k = i >> 7, n = i & 127;
        float v = W3[i];
        u16 h; asm("cvt.rn.bf16.f32 %0, %1;" : "=h"(h) : "f"(v));
        float hf = bf2f(h);
        u16 l; asm("cvt.rn.bf16.f32 %0, %1;" : "=h"(l) : "f"(v - hf));
        g_w3h[n * 256 + k] = h;
        g_w3l[n * 256 + k] = l;
    }
}

// ================= geometry =================
constexpr int BATCH = 16384;
constexpr int BT    = 8;
constexpr int MT    = 96;
constexpr int THREADS = 512;
constexpr int KB    = 32;

constexpr int AFSTR = 264;   // full A plane row stride (u16 units), conflict-free
constexpr int ASSTR = 40;    // layer-1 A slice row stride
constexpr int BSTR  = 40;    // B slice row stride

// smem layout (bytes)
constexpr int AF_HI = 0;                            // 96*264*2 = 50688
constexpr int AF_LO = 50688;                        // -> 101376
// layer-1 A slices alias AF region: [buf][plane] 96*40*2 = 7680 each
constexpr int AS_SZ = 7680;
constexpr int B_OFF = 101376;                       // [buf][plane] 256*40*2 = 20480 each
constexpr int B_SZ  = 20480;
constexpr int HC_OFF = 101376;                      // fp32 scratch aliases B (96*70*4=26880)
constexpr int HCSTR  = 70;
constexpr int AM_OFF = 183296;                      // 144 floats
constexpr int SMEM_BYTES = 184320;

// Fixed ECG graph neighbor lists (incl. self), 42 nonzeros of the 12x12 A_norm.
__device__ constexpr int NBR_OFF[13] = {0,5,11,16,20,23,26,28,31,34,37,40,42};
__device__ constexpr int NBR[42] = {
    0,1,2,3,4,
    0,1,2,3,4,5,
    0,1,2,3,5,
    0,1,2,3,
    0,1,4,
    1,2,5,
    6,7,
    6,7,8,
    7,8,9,
    8,9,10,
    9,10,11,
    10,11
};

// One KB=32 slab of the 3-term split GEMM. A: [96][astr] u16 planes; B: [N][40] u16 planes.
template<int NT>
DEV void gemm_slab(const u16* Ah, const u16* Al, int astr,
                   const u16* Bh, const u16* Bl,
                   float acc[3][NT][4], int rb, int cb, int lane)
{
    const int lr = lane >> 2;
    const int lk = (lane & 3) * 2;
    #pragma unroll
    for (int kk = 0; kk < 2; kk++) {
        const int k0 = kk * 16 + lk;
        u32 bh[NT][2], bl[NT][2];
        #pragma unroll
        for (int nt = 0; nt < NT; nt++) {
            int n = cb + nt * 8 + lr;
            bh[nt][0] = *(const u32*)(Bh + n * BSTR + k0);
            bh[nt][1] = *(const u32*)(Bh + n * BSTR + k0 + 8);
            bl[nt][0] = *(const u32*)(Bl + n * BSTR + k0);
            bl[nt][1] = *(const u32*)(Bl + n * BSTR + k0 + 8);
        }
        #pragma unroll
        for (int mt = 0; mt < 3; mt++) {
            int r = rb + mt * 16 + lr;
            u32 a0h = *(const u32*)(Ah + r * astr + k0);
            u32 a1h = *(const u32*)(Ah + (r + 8) * astr + k0);
            u32 a2h = *(const u32*)(Ah + r * astr + k0 + 8);
            u32 a3h = *(const u32*)(Ah + (r + 8) * astr + k0 + 8);
            u32 a0l = *(const u32*)(Al + r * astr + k0);
            u32 a1l = *(const u32*)(Al + (r + 8) * astr + k0);
            u32 a2l = *(const u32*)(Al + r * astr + k0 + 8);
            u32 a3l = *(const u32*)(Al + (r + 8) * astr + k0 + 8);
            #pragma unroll
            for (int nt = 0; nt < NT; nt++) {
                mma16816(acc[mt][nt], a0h, a1h, a2h, a3h, bh[nt][0], bh[nt][1]);
                mma16816(acc[mt][nt], a0h, a1h, a2h, a3h, bl[nt][0], bl[nt][1]);
                mma16816(acc[mt][nt], a0l, a1l, a2l, a3l, bh[nt][0], bh[nt][1]);
            }
        }
    }
}

// Dump D regs chunk-by-chunk, A-mix + bias(+relu), then write next-layer bf16 A planes
// (or fused mean/max epilogue on the final layer).
template<int NT, bool FINAL>
DEV void readback(unsigned char* smem, float acc[3][NT][4],
                  const float* Am, const float* __restrict__ bias,
                  float* __restrict__ out, long long obase,
                  int tid, int lane, int rg, int cg)
{
    float* Hc = (float*)(smem + HC_OFF);
    u16* afh = (u16*)(smem + AF_HI);
    u16* afl = (u16*)(smem + AF_LO);
    constexpr int NCOLS = NT * 64;   // NT=4 -> 256, NT=2 -> 128
    #pragma unroll
    for (int ch = 0; ch < NCOLS / 64; ch++) {
        const bool active = (NT == 4) ? ((cg >> 1) == ch) : ((cg >> 2) == ch);
        const int lbase = (NT == 4) ? (cg & 1) * 32 : (cg & 3) * 16;
        if (active) {
            #pragma unroll
            for (int mt = 0; mt < 3; mt++) {
                int r = rg * 48 + mt * 16 + (lane >> 2);
                #pragma unroll
                for (int nt = 0; nt < NT; nt++) {
                    int c = lbase + nt * 8 + (lane & 3) * 2;
                    *(float2*)(Hc + r * HCSTR + c) = make_float2(acc[mt][nt][0], acc[mt][nt][1]);
                    *(float2*)(Hc + (r + 8) * HCSTR + c) = make_float2(acc[mt][nt][2], acc[mt][nt][3]);
                }
            }
        }
        __syncthreads();
        if (!FINAL) {
            if (tid < 256) {
                int b = tid & 7, cp = tid >> 3;        // cp: 0..31 column pairs
                float h0[12], h1[12];
                #pragma unroll
                for (int l = 0; l < 12; l++) {
                    float2 v = *(const float2*)(Hc + (b * 12 + l) * HCSTR + cp * 2);
                    h0[l] = v.x; h1[l] = v.y;
                }
                int k0 = ch * 64 + cp * 2;
                float bv0 = __ldg(bias + k0), bv1 = __ldg(bias + k0 + 1);
                #pragma unroll
                for (int l = 0; l < 12; l++) {
                    float a0 = 0.f, a1 = 0.f;
                    #pragma unroll
                    for (int q = NBR_OFF[l]; q < NBR_OFF[l + 1]; q++) {
                        int m = NBR[q];
                        float w = Am[l * 12 + m];
                        a0 += w * h0[m];
                        a1 += w * h1[m];
                    }
                    float y0 = fmaxf(a0 + bv0, 0.f);
                    float y1 = fmaxf(a1 + bv1, 0.f);
                    int row = b * 12 + l;
                    u32 hiw = pack_bf16(y0, y1);
                    *(u32*)(afh + row * AFSTR + k0) = hiw;
                    float r0 = bf2f((u16)(hiw & 0xFFFF));
                    float r1 = bf2f((u16)(hiw >> 16));
                    *(u32*)(afl + row * AFSTR + k0) = pack_bf16(y0 - r0, y1 - r1);
                }
            }
        } else {
            int b = tid & 7, c = tid >> 3;             // c: 0..63
            int col = ch * 64 + c;
            float h[12];
            #pragma unroll
            for (int l = 0; l < 12; l++) h[l] = Hc[(b * 12 + l) * HCSTR + c];
            float bv = __ldg(bias + col);
            float sum = 0.f, mx = -3.402823466e38f;
            #pragma unroll
            for (int l = 0; l < 12; l++) {
                float a = 0.f;
                #pragma unroll
                for (int q = NBR_OFF[l]; q < NBR_OFF[l + 1]; q++)
                    a += Am[l * 12 + NBR[q]] * h[NBR[q]];
                float y = a + bv;
                sum += y;
                mx = fmaxf(mx, y);
            }
            float* op = out + (obase + b) * 256;
            op[col]       = sum * (1.0f / 12.0f);
            op[128 + col] = mx;
        }
        __syncthreads();
    }
}

__global__ void __launch_bounds__(THREADS, 1)
ecg_mma(const float* __restrict__ x,
        const float* __restrict__ b1, const float* __restrict__ b2,
        const float* __restrict__ b3, float* __restrict__ out)
{
    extern __shared__ unsigned char smem[];
    float* Am = (float*)(smem + AM_OFF);
    const u32 smem_u = (u32)__cvta_generic_to_shared(smem);

    const int tid  = threadIdx.x;
    const int lane = tid & 31;
    const int w    = tid >> 5;       // 0..15
    const int rg   = w >> 3;         // 0..1 (M group)
    const int cg   = w & 7;          // 0..7 (N group)
    const int rb   = rg * 48;
    const int cb   = cg * 32;        // N=256 layers
    const int cb3  = cg * 16;        // N=128 layer
    const long long rowbase = (long long)blockIdx.x * MT;
    const long long obase   = (long long)blockIdx.x * BT;

    if (tid == 0) {
        float a[12][12];
        for (int i = 0; i < 12; i++)
            for (int j = 0; j < 12; j++) a[i][j] = (i == j) ? 2.0f : 0.0f;
        const int ei[15] = {0,0,1,0,1,2,0,1,1,2,6,7,8,9,10};
        const int ej[15] = {1,2,2,3,3,3,4,4,5,5,7,8,9,10,11};
        for (int e = 0; e < 15; e++) { a[ei[e]][ej[e]] = 1.0f; a[ej[e]][ei[e]] = 1.0f; }
        float dinv[12];
        for (int i = 0; i < 12; i++) {
            float s = 0.f;
            for (int j = 0; j < 12; j++) s += a[i][j];
            dinv[i] = 1.0f / sqrtf(s);
        }
        for (int i = 0; i < 12; i++)
            for (int j = 0; j < 12; j++)
                Am[i * 12 + j] = dinv[i] * a[i][j] * dinv[j];
    }

    // B staging thread roles (N=256 layers): n = tid>>1 (0..255), half = tid&1
    const int bn = tid >> 1, bhf = tid & 1;
    // N=128 layer: n = tid>>2 (0..127), q = tid&3
    const int bn3 = tid >> 2, bq3 = tid & 3;
    // layer-1 A staging: row = tid>>2 (0..95 active), q = tid&3 -> 8 k each
    const int xr = tid >> 2, xq = tid & 3;
    const bool xact = tid < MT * 4;

    u16* ashi[2] = {(u16*)(smem + 0),         (u16*)(smem + 2 * AS_SZ)};
    u16* aslo[2] = {(u16*)(smem + AS_SZ),     (u16*)(smem + 3 * AS_SZ)};
    u16* bshi[2] = {(u16*)(smem + B_OFF),             (u16*)(smem + B_OFF + 2 * B_SZ)};
    u16* bslo[2] = {(u16*)(smem + B_OFF + B_SZ),      (u16*)(smem + B_OFF + 3 * B_SZ)};
    const u32 b_u  = smem_u + B_OFF;
    const u32 as_u = smem_u;

    float acc[3][4][4];
    #pragma unroll
    for (int i = 0; i < 3; i++)
        #pragma unroll
        for (int j = 0; j < 4; j++)
            #pragma unroll
            for (int v = 0; v < 4; v++) acc[i][j][v] = 0.f;

    // ---------------- Layer 1: X(96x512) @ W1 (K=512, 16 slabs) ----------------
    {
        // preload slab 0: B via cp.async, A via convert+STS
        cpa16(b_u + bn * 80 + bhf * 32,            (const char*)(g_w1h + bn * 512 + bhf * 16) );
        cpa16(b_u + bn * 80 + bhf * 32 + 16,       (const char*)(g_w1h + bn * 512 + bhf * 16 + 8));
        cpa16(b_u + B_SZ + bn * 80 + bhf * 32,     (const char*)(g_w1l + bn * 512 + bhf * 16));
        cpa16(b_u + B_SZ + bn * 80 + bhf * 32 + 16,(const char*)(g_w1l + bn * 512 + bhf * 16 + 8));
        cpa_commit();
        if (xact) {
            float4 v0 = *(const float4*)(x + (rowbase + xr) * 512 + xq * 8);
            float4 v1 = *(const float4*)(x + (rowbase + xr) * 512 + xq * 8 + 4);
            float vals[8] = {v0.x,v0.y,v0.z,v0.w, v1.x,v1.y,v1.z,v1.w};
            #pragma unroll
            for (int i = 0; i < 4; i++) {
                u32 hiw = pack_bf16(vals[2*i], vals[2*i+1]);
                *(u32*)(ashi[0] + xr * ASSTR + xq * 8 + 2 * i) = hiw;
                float r0 = bf2f((u16)(hiw & 0xFFFF));
                float r1 = bf2f((u16)(hiw >> 16));
                *(u32*)(aslo[0] + xr * ASSTR + xq * 8 + 2 * i) = pack_bf16(vals[2*i] - r0, vals[2*i+1] - r1);
            }
        }
        cpa_wait0();
        __syncthreads();

        for (int it = 0; it < 16; it++) {
            const int cur = it & 1, nxt = cur ^ 1;
            const bool more = it < 15;
            float4 v0, v1;
            if (more) {
                const u32 bb = b_u + nxt * 2 * B_SZ;
                cpa16(bb + bn * 80 + bhf * 32,        (const char*)(g_w1h + bn * 512 + (it+1) * 32 + bhf * 16));
                cpa16(bb + bn * 80 + bhf * 32 + 16,   (const char*)(g_w1h + bn * 512 + (it+1) * 32 + bhf * 16 + 8));
                cpa16(bb + B_SZ + bn * 80 + bhf * 32, (const char*)(g_w1l + bn * 512 + (it+1) * 32 + bhf * 16));
                cpa16(bb + B_SZ + bn * 80 + bhf * 32 + 16, (const char*)(g_w1l + bn * 512 + (it+1) * 32 + bhf * 16 + 8));
                cpa_commit();
                if (xact) {
                    v0 = *(const float4*)(x + (rowbase + xr) * 512 + (it+1) * 32 + xq * 8);
                    v1 = *(const float4*)(x + (rowbase + xr) * 512 + (it+1) * 32 + xq * 8 + 4);
                }
            }
            gemm_slab<4>(ashi[cur], aslo[cur], ASSTR, bshi[cur], bslo[cur], acc, rb, cb, lane);
            if (more) {
                if (xact) {
                    float vals[8] = {v0.x,v0.y,v0.z,v0.w, v1.x,v1.y,v1.z,v1.w};
                    #pragma unroll
                    for (int i = 0; i < 4; i++) {
                        u32 hiw = pack_bf16(vals[2*i], vals[2*i+1]);
                        *(u32*)(ashi[nxt] + xr * ASSTR + xq * 8 + 2 * i) = hiw;
                        float r0 = bf2f((u16)(hiw & 0xFFFF));
                        float r1 = bf2f((u16)(hiw >> 16));
                        *(u32*)(aslo[nxt] + xr * ASSTR + xq * 8 + 2 * i) = pack_bf16(vals[2*i] - r0, vals[2*i+1] - r1);
                    }
                }
                cpa_wait0();
            }
            __syncthreads();
        }
    }
    readback<4, false>(smem, acc, Am, b1, out, obase, tid, lane, rg, cg);

    // ---------------- Layer 2: H1(96x256) @ W2 (K=256, 8 slabs) ----------------
    #pragma unroll
    for (int i = 0; i < 3; i++)
        #pragma unroll
        for (int j = 0; j < 4; j++)
            #pragma unroll
            for (int v = 0; v < 4; v++) acc[i][j][v] = 0.f;
    {
        u16* afh = (u16*)(smem + AF_HI);
        u16* afl = (u16*)(smem + AF_LO);
        cpa16(b_u + bn * 80 + bhf * 32,            (const char*)(g_w2h + bn * 256 + bhf * 16));
        cpa16(b_u + bn * 80 + bhf * 32 + 16,       (const char*)(g_w2h + bn * 256 + bhf * 16 + 8));
        cpa16(b_u + B_SZ + bn * 80 + bhf * 32,     (const char*)(g_w2l + bn * 256 + bhf * 16));
        cpa16(b_u + B_SZ + bn * 80 + bhf * 32 + 16,(const char*)(g_w2l + bn * 256 + bhf * 16 + 8));
        cpa_commit();
        cpa_wait0();
        __syncthreads();
        for (int it = 0; it < 8; it++) {
            const int cur = it & 1, nxt = cur ^ 1;
            const bool more = it < 7;
            if (more) {
                const u32 bb = b_u + nxt * 2 * B_SZ;
                cpa16(bb + bn * 80 + bhf * 32,        (const char*)(g_w2h + bn * 256 + (it+1) * 32 + bhf * 16));
                cpa16(bb + bn * 80 + bhf * 32 + 16,   (const char*)(g_w2h + bn * 256 + (it+1) * 32 + bhf * 16 + 8));
                cpa16(bb + B_SZ + bn * 80 + bhf * 32, (const char*)(g_w2l + bn * 256 + (it+1) * 32 + bhf * 16));
                cpa16(bb + B_SZ + bn * 80 + bhf * 32 + 16, (const char*)(g_w2l + bn * 256 + (it+1) * 32 + bhf * 16 + 8));
                cpa_commit();
            }
            gemm_slab<4>(afh + it * 32, afl + it * 32, AFSTR, bshi[cur], bslo[cur], acc, rb, cb, lane);
            if (more) cpa_wait0();
            __syncthreads();
        }
    }
    readback<4, false>(smem, acc, Am, b2, out, obase, tid, lane, rg, cg);

    // ---------------- Layer 3: H2(96x256) @ W3 (K=256, 8 slabs, N=128) ----------------
    float acc3[3][2][4];
    #pragma unroll
    for (int i = 0; i < 3; i++)
        #pragma unroll
        for (int j = 0; j < 2; j++)
            #pragma unroll
            for (int v = 0; v < 4; v++) acc3[i][j][v] = 0.f;
    {
        u16* afh = (u16*)(smem + AF_HI);
        u16* afl = (u16*)(smem + AF_LO);
        cpa16(b_u + bn3 * 80 + bq3 * 16,        (const char*)(g_w3h + bn3 * 256 + bq3 * 8));
        cpa16(b_u + B_SZ + bn3 * 80 + bq3 * 16, (const char*)(g_w3l + bn3 * 256 + bq3 * 8));
        cpa_commit();
        cpa_wait0();
        __syncthreads();
        for (int it = 0; it < 8; it++) {
            const int cur = it & 1, nxt = cur ^ 1;
            const bool more = it < 7;
            if (more) {
                const u32 bb = b_u + nxt * 2 * B_SZ;
                cpa16(bb + bn3 * 80 + bq3 * 16,        (const char*)(g_w3h + bn3 * 256 + (it+1) * 32 + bq3 * 8));
                cpa16(bb + B_SZ + bn3 * 80 + bq3 * 16, (const char*)(g_w3l + bn3 * 256 + (it+1) * 32 + bq3 * 8));
                cpa_commit();
            }
            gemm_slab<2>(afh + it * 32, afl + it * 32, AFSTR, bshi[cur], bslo[cur], acc3, rb, cb3, lane);
            if (more) cpa_wait0();
            __syncthreads();
        }
    }
    readback<2, true>(smem, acc3, Am, b3, out, obase, tid, lane, rg, cg);
}

extern "C" void kernel_launch(void* const* d_in, const int* in_sizes, int n_in,
                              void* d_out, int out_size)
{
    const float* x  = (const float*)d_in[0];
    const float* W1 = (const float*)d_in[1];
    const float* b1 = (const float*)d_in[2];
    const float* W2 = (const float*)d_in[3];
    const float* b2 = (const float*)d_in[4];
    const float* W3 = (const float*)d_in[5];
    const float* b3 = (const float*)d_in[6];
    float* out = (float*)d_out;

    conv_w<<<148, 512>>>(W1, W2, W3);

    cudaFuncSetAttribute(ecg_mma, cudaFuncAttributeMaxDynamicSharedMemorySize, SMEM_BYTES);
    ecg_mma<<<BATCH / BT, THREADS, SMEM_BYTES>>>(x, b1, b2, b3, out);
}